// round 2
// baseline (speedup 1.0000x reference)
#include <cuda_runtime.h>
#include <cuda_bf16.h>
#include <math.h>
#include <stdint.h>

#define B_ 32
#define S_ 1024
#define D_ 512
#define H_ 8
#define DH_ 64
#define L_ 3
#define FF_ 2048
#define C_ 6
#define BS_ (B_*S_)

// ---------------- scratch (device globals; no allocations allowed) ----------
static __device__ float g_x[(size_t)BS_*D_];          // residual stream
static __device__ float g_qkv[(size_t)BS_*3*D_];
static __device__ float g_scores[(size_t)B_*H_*S_*S_];
static __device__ float g_o[(size_t)BS_*D_];
static __device__ float g_p[(size_t)BS_*D_];
static __device__ float g_pool[B_*D_];
static __device__ float g_h1[B_*FF_];
// bf16 hi/lo split buffers
static __device__ uint16_t g_ah[(size_t)BS_*D_];
static __device__ uint16_t g_al[(size_t)BS_*D_];
static __device__ uint16_t g_wh[(size_t)D_*3*D_];
static __device__ uint16_t g_wl[(size_t)D_*3*D_];

// ---------------- mma helpers -----------------------------------------------
__device__ __forceinline__ uint32_t s2u(const void* p) {
    return (uint32_t)__cvta_generic_to_shared(p);
}
#define LDSM4(R, addr) \
    asm volatile("ldmatrix.sync.aligned.m8n8.x4.shared.b16 {%0,%1,%2,%3}, [%4];" \
        : "=r"((R)[0]), "=r"((R)[1]), "=r"((R)[2]), "=r"((R)[3]) : "r"(addr))
#define LDSM4T(R, addr) \
    asm volatile("ldmatrix.sync.aligned.m8n8.x4.trans.shared.b16 {%0,%1,%2,%3}, [%4];" \
        : "=r"((R)[0]), "=r"((R)[1]), "=r"((R)[2]), "=r"((R)[3]) : "r"(addr))
#define MMA_BF16(c, a, b) \
    asm volatile("mma.sync.aligned.m16n8k16.row.col.f32.bf16.bf16.f32 " \
        "{%0,%1,%2,%3},{%4,%5,%6,%7},{%8,%9},{%0,%1,%2,%3};" \
        : "+f"((c)[0]), "+f"((c)[1]), "+f"((c)[2]), "+f"((c)[3]) \
        : "r"((a)[0]), "r"((a)[1]), "r"((a)[2]), "r"((a)[3]), "r"((b)[0]), "r"((b)[1]))

// ---------------- fp32 -> bf16 hi/lo split ----------------------------------
__global__ void __launch_bounds__(256) convert_hl(const float* __restrict__ in,
                                                  uint16_t* __restrict__ hi,
                                                  uint16_t* __restrict__ lo) {
    int i = blockIdx.x * 256 + threadIdx.x;     // one float4 per thread
    float4 v = ((const float4*)in)[i];
    float f[4] = {v.x, v.y, v.z, v.w};
    ushort4 ph, pl;
    unsigned short* hh = (unsigned short*)&ph;
    unsigned short* ll = (unsigned short*)&pl;
    #pragma unroll
    for (int j = 0; j < 4; j++) {
        __nv_bfloat16 h = __float2bfloat16(f[j]);
        float hf = __bfloat162float(h);
        __nv_bfloat16 l = __float2bfloat16(f[j] - hf);
        hh[j] = *(unsigned short*)&h;
        ll[j] = *(unsigned short*)&l;
    }
    ((ushort4*)hi)[i] = ph;
    ((ushort4*)lo)[i] = pl;
}

// ---------------- 128x128 block bf16x3 tensor-core GEMM ----------------------
// C[M,N] = A[M,K] @ B[K,N] + bias, via Ah*Bh + Ah*Bl + Al*Bh (fp32 accum)
// grid (N/128, M/128), 256 threads (8 warps, 2x4 warp grid), K multiple of 32.
#define AST 40      // A smem row stride (bf16), 80B = 5*16B, bank-conflict-free
#define BST 136     // B smem row stride (bf16), 272B = 17*16B
__global__ void __launch_bounds__(256) gemm_bf16x3(
    const uint16_t* __restrict__ Ah, const uint16_t* __restrict__ Al,
    const uint16_t* __restrict__ Bh, const uint16_t* __restrict__ Bl,
    const float* __restrict__ bias, float* __restrict__ C, int N, int K) {
    __shared__ __align__(16) uint16_t sA[2][128 * AST];
    __shared__ __align__(16) uint16_t sB[2][32 * BST];
    const int tid = threadIdx.x;
    const int lane = tid & 31, warp = tid >> 5;
    const int wr = warp >> 2, wc = warp & 3;
    const size_t aRow0 = (size_t)blockIdx.y * 128;
    const int bCol0 = blockIdx.x * 128;
    const int lrow = lane & 15, lseg = lane >> 4;

    float acc[16][4];
    #pragma unroll
    for (int i = 0; i < 16; i++)
        #pragma unroll
        for (int j = 0; j < 4; j++) acc[i][j] = 0.f;

    for (int kt = 0; kt < K; kt += 32) {
        #pragma unroll
        for (int i = 0; i < 2; i++) {
            int s = tid * 2 + i;                 // 0..511
            int ar = s >> 2, aseg = s & 3;       // A: 128 rows x 4 segs
            *(uint4*)&sA[0][ar * AST + aseg * 8] =
                *(const uint4*)(Ah + (aRow0 + ar) * K + kt + aseg * 8);
            *(uint4*)&sA[1][ar * AST + aseg * 8] =
                *(const uint4*)(Al + (aRow0 + ar) * K + kt + aseg * 8);
            int br = s >> 4, bseg = s & 15;      // B: 32 rows x 16 segs
            *(uint4*)&sB[0][br * BST + bseg * 8] =
                *(const uint4*)(Bh + (size_t)(kt + br) * N + bCol0 + bseg * 8);
            *(uint4*)&sB[1][br * BST + bseg * 8] =
                *(const uint4*)(Bl + (size_t)(kt + br) * N + bCol0 + bseg * 8);
        }
        __syncthreads();
        #pragma unroll
        for (int k16 = 0; k16 < 32; k16 += 16) {
            uint32_t ah[4][4], al[4][4], bh[4][2], bl[4][2];
            #pragma unroll
            for (int mi = 0; mi < 4; mi++) {
                int r = wr * 64 + mi * 16 + lrow;
                int c = k16 + lseg * 8;
                LDSM4(ah[mi], s2u(&sA[0][r * AST + c]));
                LDSM4(al[mi], s2u(&sA[1][r * AST + c]));
            }
            #pragma unroll
            for (int np = 0; np < 2; np++) {
                int r = k16 + lrow;
                int c = wc * 32 + np * 16 + lseg * 8;
                uint32_t t4[4];
                LDSM4T(t4, s2u(&sB[0][r * BST + c]));
                bh[np*2][0] = t4[0]; bh[np*2][1] = t4[1];
                bh[np*2+1][0] = t4[2]; bh[np*2+1][1] = t4[3];
                LDSM4T(t4, s2u(&sB[1][r * BST + c]));
                bl[np*2][0] = t4[0]; bl[np*2][1] = t4[1];
                bl[np*2+1][0] = t4[2]; bl[np*2+1][1] = t4[3];
            }
            #pragma unroll
            for (int mi = 0; mi < 4; mi++)
                #pragma unroll
                for (int ni = 0; ni < 4; ni++) {
                    float* c = acc[mi * 4 + ni];
                    MMA_BF16(c, ah[mi], bh[ni]);
                    MMA_BF16(c, ah[mi], bl[ni]);
                    MMA_BF16(c, al[mi], bh[ni]);
                }
        }
        __syncthreads();
    }
    #pragma unroll
    for (int mi = 0; mi < 4; mi++) {
        size_t row = aRow0 + wr * 64 + mi * 16 + (lane >> 2);
        #pragma unroll
        for (int ni = 0; ni < 4; ni++) {
            int col = bCol0 + wc * 32 + ni * 8 + (lane & 3) * 2;
            float b0 = 0.f, b1 = 0.f;
            if (bias) { b0 = bias[col]; b1 = bias[col + 1]; }
            float* c = acc[mi * 4 + ni];
            *(float2*)&C[row * N + col] = make_float2(c[0] + b0, c[1] + b1);
            *(float2*)&C[(row + 8) * N + col] = make_float2(c[2] + b0, c[3] + b1);
        }
    }
}

// ---------------- embedding + sinusoidal PE ---------------------------------
__global__ void __launch_bounds__(256) embed_kernel(const int* __restrict__ tokens,
                                                    const float* __restrict__ emb) {
    int idx = blockIdx.x * 256 + threadIdx.x;
    int d = idx & (D_ - 1);
    int bs = idx >> 9;
    int s = bs & (S_ - 1);
    int tok = tokens[bs];
    float div = expf((float)(d & ~1) * (-9.210340371976184f / (float)D_));
    float ang = (float)s * div;
    float pe = (d & 1) ? cosf(ang) : sinf(ang);
    g_x[idx] = emb[(size_t)tok * D_ + d] + pe;
}

// ---------------- QK^T ------------------------------------------------------
__global__ void __launch_bounds__(256) qk_kernel() {
    int bh = blockIdx.z;
    int b = bh >> 3, h = bh & 7;
    int sq0 = blockIdx.y * 64, sk0 = blockIdx.x * 64;
    __shared__ float Qs[64][64];
    __shared__ float Ks[64][64];
    int tid = threadIdx.x;
    const float* qb = g_qkv + ((size_t)(b * S_ + sq0)) * 1536 + h * 192;
    const float* kb = g_qkv + ((size_t)(b * S_ + sk0)) * 1536 + h * 192 + 64;
    #pragma unroll
    for (int it = 0; it < 4; it++) {
        int lin = tid + it * 256;
        int row = lin >> 4;
        int c4 = (lin & 15) << 2;
        float4 q4 = *(const float4*)(qb + (size_t)row * 1536 + c4);
        Qs[c4+0][row] = q4.x; Qs[c4+1][row] = q4.y; Qs[c4+2][row] = q4.z; Qs[c4+3][row] = q4.w;
        float4 k4 = *(const float4*)(kb + (size_t)row * 1536 + c4);
        Ks[c4+0][row] = k4.x; Ks[c4+1][row] = k4.y; Ks[c4+2][row] = k4.z; Ks[c4+3][row] = k4.w;
    }
    __syncthreads();
    int tx = tid & 15, ty = tid >> 4;
    float acc[4][4];
    #pragma unroll
    for (int i = 0; i < 4; i++)
        #pragma unroll
        for (int j = 0; j < 4; j++) acc[i][j] = 0.f;
    #pragma unroll 16
    for (int d = 0; d < 64; d++) {
        float4 ra = *(float4*)&Qs[d][ty*4];
        float4 rb = *(float4*)&Ks[d][tx*4];
        float a[4] = {ra.x, ra.y, ra.z, ra.w};
        float c[4] = {rb.x, rb.y, rb.z, rb.w};
        #pragma unroll
        for (int i = 0; i < 4; i++)
            #pragma unroll
            for (int j = 0; j < 4; j++)
                acc[i][j] = fmaf(a[i], c[j], acc[i][j]);
    }
    float* srow = g_scores + ((size_t)bh * S_ + sq0 + ty*4) * S_ + sk0 + tx*4;
    #pragma unroll
    for (int i = 0; i < 4; i++) {
        float4 w = make_float4(acc[i][0]*0.125f, acc[i][1]*0.125f,
                               acc[i][2]*0.125f, acc[i][3]*0.125f);
        *(float4*)(srow + (size_t)i * S_) = w;
    }
}

// ---------------- row softmax ------------------------------------------------
__global__ void __launch_bounds__(256) softmax_kernel() {
    size_t row = blockIdx.x;
    float* p = g_scores + row * S_;
    int tid = threadIdx.x;
    float4 v = *(float4*)(p + tid * 4);
    float m = fmaxf(fmaxf(v.x, v.y), fmaxf(v.z, v.w));
    #pragma unroll
    for (int o = 16; o; o >>= 1) m = fmaxf(m, __shfl_xor_sync(0xffffffffu, m, o));
    __shared__ float sm[8], ss[8];
    if ((tid & 31) == 0) sm[tid >> 5] = m;
    __syncthreads();
    m = sm[0];
    #pragma unroll
    for (int w = 1; w < 8; w++) m = fmaxf(m, sm[w]);
    v.x = __expf(v.x - m); v.y = __expf(v.y - m);
    v.z = __expf(v.z - m); v.w = __expf(v.w - m);
    float s = v.x + v.y + v.z + v.w;
    #pragma unroll
    for (int o = 16; o; o >>= 1) s += __shfl_xor_sync(0xffffffffu, s, o);
    if ((tid & 31) == 0) ss[tid >> 5] = s;
    __syncthreads();
    s = 0.f;
    #pragma unroll
    for (int w = 0; w < 8; w++) s += ss[w];
    float inv = 1.0f / s;
    v.x *= inv; v.y *= inv; v.z *= inv; v.w *= inv;
    *(float4*)(p + tid * 4) = v;
}

// ---------------- AV ---------------------------------------------------------
__global__ void __launch_bounds__(256) av_kernel() {
    int bh = blockIdx.y;
    int b = bh >> 3, h = bh & 7;
    int sq0 = blockIdx.x * 64;
    __shared__ float Ps[64][64];
    __shared__ float Vs[64][64];
    int tid = threadIdx.x;
    int tx = tid & 15, ty = tid >> 4;
    float acc[4][4];
    #pragma unroll
    for (int i = 0; i < 4; i++)
        #pragma unroll
        for (int j = 0; j < 4; j++) acc[i][j] = 0.f;
    const float* prow = g_scores + ((size_t)bh * S_ + sq0) * S_;
    const float* vb = g_qkv + ((size_t)(b * S_)) * 1536 + h * 192 + 128;
    for (int k0 = 0; k0 < S_; k0 += 64) {
        #pragma unroll
        for (int it = 0; it < 4; it++) {
            int lin = tid + it * 256;
            int row = lin >> 4;
            int c4 = (lin & 15) << 2;
            float4 p4 = *(const float4*)(prow + (size_t)row * S_ + k0 + c4);
            Ps[c4+0][row] = p4.x; Ps[c4+1][row] = p4.y; Ps[c4+2][row] = p4.z; Ps[c4+3][row] = p4.w;
            float4 v4 = *(const float4*)(vb + (size_t)(k0 + row) * 1536 + c4);
            *(float4*)&Vs[row][c4] = v4;
        }
        __syncthreads();
        #pragma unroll 16
        for (int kk = 0; kk < 64; kk++) {
            float4 ra = *(float4*)&Ps[kk][ty*4];
            float4 rb = *(float4*)&Vs[kk][tx*4];
            float a[4] = {ra.x, ra.y, ra.z, ra.w};
            float c[4] = {rb.x, rb.y, rb.z, rb.w};
            #pragma unroll
            for (int i = 0; i < 4; i++)
                #pragma unroll
                for (int j = 0; j < 4; j++)
                    acc[i][j] = fmaf(a[i], c[j], acc[i][j]);
        }
        __syncthreads();
    }
    float* ob = g_o + ((size_t)(b * S_ + sq0 + ty*4)) * D_ + h * 64 + tx * 4;
    #pragma unroll
    for (int i = 0; i < 4; i++) {
        float4 w = make_float4(acc[i][0], acc[i][1], acc[i][2], acc[i][3]);
        *(float4*)(ob + (size_t)i * D_) = w;
    }
}

// ---------------- residual + bias + LayerNorm --------------------------------
__global__ void __launch_bounds__(128) ln_kernel(const float* __restrict__ bias,
                                                 const float* __restrict__ gamma,
                                                 const float* __restrict__ beta) {
    size_t r = blockIdx.x;
    int tid = threadIdx.x;
    float4 o = *(float4*)(g_p + r * D_ + tid * 4);
    float4 xr = *(float4*)(g_x + r * D_ + tid * 4);
    float4 bb = *(const float4*)(bias + tid * 4);
    float4 y;
    y.x = o.x + xr.x + bb.x; y.y = o.y + xr.y + bb.y;
    y.z = o.z + xr.z + bb.z; y.w = o.w + xr.w + bb.w;
    __shared__ float sm[4], ss[4];
    float s = y.x + y.y + y.z + y.w;
    #pragma unroll
    for (int o2 = 16; o2; o2 >>= 1) s += __shfl_xor_sync(0xffffffffu, s, o2);
    if ((tid & 31) == 0) sm[tid >> 5] = s;
    __syncthreads();
    float mean = (sm[0] + sm[1] + sm[2] + sm[3]) * (1.0f / D_);
    float dx = y.x - mean, dy = y.y - mean, dz = y.z - mean, dw = y.w - mean;
    float sq = dx*dx + dy*dy + dz*dz + dw*dw;
    #pragma unroll
    for (int o2 = 16; o2; o2 >>= 1) sq += __shfl_xor_sync(0xffffffffu, sq, o2);
    if ((tid & 31) == 0) ss[tid >> 5] = sq;
    __syncthreads();
    float var = (ss[0] + ss[1] + ss[2] + ss[3]) * (1.0f / D_);
    float inv = rsqrtf(var + 1e-5f);
    float4 g = *(const float4*)(gamma + tid * 4);
    float4 be = *(const float4*)(beta + tid * 4);
    float4 out;
    out.x = dx * inv * g.x + be.x; out.y = dy * inv * g.y + be.y;
    out.z = dz * inv * g.z + be.z; out.w = dw * inv * g.w + be.w;
    *(float4*)(g_x + r * D_ + tid * 4) = out;
}

// ---------------- mean pool --------------------------------------------------
__global__ void __launch_bounds__(512) pool_kernel() {
    int b = blockIdx.x, d = threadIdx.x;
    const float* base = g_x + (size_t)b * S_ * D_ + d;
    float s = 0.f;
    for (int i = 0; i < S_; i++) s += base[(size_t)i * D_];
    g_pool[b * D_ + d] = s * (1.0f / S_);
}

// ---------------- MLP --------------------------------------------------------
__global__ void __launch_bounds__(256) mlp1_kernel(const float* __restrict__ w,
                                                   const float* __restrict__ bias) {
    int f = blockIdx.x * 256 + threadIdx.x;
    int b = blockIdx.y;
    float acc = bias[f];
    const float* pr = g_pool + b * D_;
    for (int d = 0; d < D_; d++) acc = fmaf(pr[d], w[(size_t)d * FF_ + f], acc);
    g_h1[b * FF_ + f] = fmaxf(acc, 0.f);
}

__global__ void __launch_bounds__(192) mlp2_kernel(const float* __restrict__ w,
                                                   const float* __restrict__ bias,
                                                   float* __restrict__ out) {
    int t = threadIdx.x;
    int b = t / C_, c = t % C_;
    float acc = bias[c];
    const float* hr = g_h1 + b * FF_;
    for (int f = 0; f < FF_; f++) acc = fmaf(hr[f], w[f * C_ + c], acc);
    out[b * C_ + c] = acc;
}

// ---------------- launch ------------------------------------------------------
extern "C" void kernel_launch(void* const* d_in, const int* in_sizes, int n_in,
                              void* d_out, int out_size) {
    const int*   tokens = (const int*)d_in[0];
    const float* emb    = (const float*)d_in[1];
    const float* qkv_w  = (const float*)d_in[2];
    const float* qkv_b  = (const float*)d_in[3];
    const float* fc_w   = (const float*)d_in[4];
    const float* fc_b   = (const float*)d_in[5];
    const float* gamma  = (const float*)d_in[6];
    const float* beta   = (const float*)d_in[7];
    const float* fc1_w  = (const float*)d_in[8];
    const float* fc1_b  = (const float*)d_in[9];
    const float* fc2_w  = (const float*)d_in[10];
    const float* fc2_b  = (const float*)d_in[11];
    float* out = (float*)d_out;
    (void)in_sizes; (void)n_in; (void)out_size;

    float *x, *qkv, *o, *p;
    uint16_t *ah, *al, *wh, *wl;
    cudaGetSymbolAddress((void**)&x,   g_x);
    cudaGetSymbolAddress((void**)&qkv, g_qkv);
    cudaGetSymbolAddress((void**)&o,   g_o);
    cudaGetSymbolAddress((void**)&p,   g_p);
    cudaGetSymbolAddress((void**)&ah,  g_ah);
    cudaGetSymbolAddress((void**)&al,  g_al);
    cudaGetSymbolAddress((void**)&wh,  g_wh);
    cudaGetSymbolAddress((void**)&wl,  g_wl);

    embed_kernel<<<(BS_ * D_) / 256, 256>>>(tokens, emb);

    for (int l = 0; l < L_; l++) {
        // split x and qkv weights to bf16 hi/lo
        convert_hl<<<(BS_ * D_) / 1024, 256>>>(x, ah, al);
        convert_hl<<<(D_ * 3 * D_) / 1024, 256>>>(qkv_w + (size_t)l * D_ * 3 * D_, wh, wl);
        // qkv = x @ qkv_w[l] + qkv_b[l]  (tensor cores, bf16x3)
        gemm_bf16x3<<<dim3(3 * D_ / 128, BS_ / 128), 256>>>(
            ah, al, wh, wl, qkv_b + (size_t)l * 3 * D_, qkv, 3 * D_, D_);
        // attention (fp32)
        qk_kernel<<<dim3(S_ / 64, S_ / 64, B_ * H_), 256>>>();
        softmax_kernel<<<B_ * H_ * S_, 256>>>();
        av_kernel<<<dim3(S_ / 64, B_ * H_), 256>>>();
        // projection (bias folded into LN)
        convert_hl<<<(BS_ * D_) / 1024, 256>>>(o, ah, al);
        convert_hl<<<(D_ * D_) / 1024, 256>>>(fc_w + (size_t)l * D_ * D_, wh, wl);
        gemm_bf16x3<<<dim3(D_ / 128, BS_ / 128), 256>>>(
            ah, al, wh, wl, (const float*)nullptr, p, D_, D_);
        // x = LN(p + fc_b[l] + x)
        ln_kernel<<<BS_, 128>>>(fc_b + (size_t)l * D_, gamma, beta);
    }

    pool_kernel<<<B_, 512>>>();
    mlp1_kernel<<<dim3(FF_ / 256, B_), 256>>>(fc1_w, fc1_b);
    mlp2_kernel<<<1, B_ * C_>>>(fc2_w, fc2_b, out);
}

// round 4
// speedup vs baseline: 8.5642x; 8.5642x over previous
#include <cuda_runtime.h>
#include <cuda_bf16.h>
#include <math.h>
#include <stdint.h>

#define B_ 32
#define S_ 1024
#define D_ 512
#define H_ 8
#define L_ 3
#define FF_ 2048
#define C_ 6
#define BS_ (B_*S_)

// ---------------- scratch (device globals) ----------------------------------
static __device__ float          g_x[(size_t)BS_*D_];        // residual fp32
static __device__ __nv_bfloat16  g_xb[(size_t)BS_*D_];       // residual bf16
static __device__ __nv_bfloat16  g_qkvb[(size_t)BS_*3*D_];   // qkv bf16
static __device__ __nv_bfloat16  g_ob[(size_t)BS_*D_];       // attn out bf16
static __device__ float          g_p[(size_t)BS_*D_];        // proj out fp32
static __device__ float          g_pool[B_*D_];
static __device__ float          g_h1[B_*FF_];
static __device__ uint16_t       g_wh[(size_t)D_*3*D_];      // weight hi
static __device__ uint16_t       g_wl[(size_t)D_*3*D_];      // weight lo

// ---------------- asm helpers ------------------------------------------------
__device__ __forceinline__ uint32_t s2u(const void* p) {
    return (uint32_t)__cvta_generic_to_shared(p);
}
#define LDSM4(R, addr) \
    asm volatile("ldmatrix.sync.aligned.m8n8.x4.shared.b16 {%0,%1,%2,%3}, [%4];" \
        : "=r"((R)[0]), "=r"((R)[1]), "=r"((R)[2]), "=r"((R)[3]) : "r"(addr))
#define LDSM4T(R, addr) \
    asm volatile("ldmatrix.sync.aligned.m8n8.x4.trans.shared.b16 {%0,%1,%2,%3}, [%4];" \
        : "=r"((R)[0]), "=r"((R)[1]), "=r"((R)[2]), "=r"((R)[3]) : "r"(addr))
#define MMA_BF16(c, a, b) \
    asm volatile("mma.sync.aligned.m16n8k16.row.col.f32.bf16.bf16.f32 " \
        "{%0,%1,%2,%3},{%4,%5,%6,%7},{%8,%9},{%0,%1,%2,%3};" \
        : "+f"((c)[0]), "+f"((c)[1]), "+f"((c)[2]), "+f"((c)[3]) \
        : "r"((a)[0]), "r"((a)[1]), "r"((a)[2]), "r"((a)[3]), "r"((b)[0]), "r"((b)[1]))
#define CP16(dst, src) \
    asm volatile("cp.async.cg.shared.global [%0], [%1], 16;" :: "r"(dst), "l"(src))
#define CP_COMMIT asm volatile("cp.async.commit_group;")
#define CP_WAIT(n) asm volatile("cp.async.wait_group %0;" :: "n"(n))

// ---------------- fp32 -> bf16 hi/lo split (weights) -------------------------
__global__ void __launch_bounds__(256) convert_hl(const float* __restrict__ in,
                                                  uint16_t* __restrict__ hi,
                                                  uint16_t* __restrict__ lo) {
    int i = blockIdx.x * 256 + threadIdx.x;
    float4 v = ((const float4*)in)[i];
    float f[4] = {v.x, v.y, v.z, v.w};
    ushort4 ph, pl;
    unsigned short* hh = (unsigned short*)&ph;
    unsigned short* ll = (unsigned short*)&pl;
    #pragma unroll
    for (int j = 0; j < 4; j++) {
        __nv_bfloat16 h = __float2bfloat16(f[j]);
        float hf = __bfloat162float(h);
        __nv_bfloat16 l = __float2bfloat16(f[j] - hf);
        hh[j] = *(unsigned short*)&h;
        ll[j] = *(unsigned short*)&l;
    }
    ((ushort4*)hi)[i] = ph;
    ((ushort4*)lo)[i] = pl;
}

// ---------------- pipelined bf16x2 GEMM --------------------------------------
// C = A(bf16)[M,K] @ (Wh+Wl)[K,N] + bias. 128x128 tile, cp.async double buffer.
#define AST 40
#define BST 136
#define A_EL (128*AST)
#define B_EL (32*BST)
#define GSMEM ((2*A_EL + 4*B_EL) * 2)   // 55296 bytes
__global__ void __launch_bounds__(256, 2) gemm_bf16x2(
    const __nv_bfloat16* __restrict__ A,
    const uint16_t* __restrict__ Bh, const uint16_t* __restrict__ Bl,
    const float* __restrict__ bias,
    float* __restrict__ Cf, __nv_bfloat16* __restrict__ Cb, int N, int K) {
    extern __shared__ __align__(16) uint16_t sm_[];
    uint16_t* sA  = sm_;                  // 2 stages x 128 x AST
    uint16_t* sBh = sm_ + 2 * A_EL;       // 2 stages x 32 x BST
    uint16_t* sBl = sBh + 2 * B_EL;
    const int tid = threadIdx.x;
    const int lane = tid & 31, warp = tid >> 5;
    const int wr = warp >> 2, wc = warp & 3;
    const size_t aRow0 = (size_t)blockIdx.y * 128;
    const int bCol0 = blockIdx.x * 128;
    const int lrow = lane & 15, lseg = lane >> 4;

    float acc[16][4];
    #pragma unroll
    for (int i = 0; i < 16; i++)
        #pragma unroll
        for (int j = 0; j < 4; j++) acc[i][j] = 0.f;

    const int nk = K / 32;
    // stage loader
    auto load_stage = [&](int st, int kt) {
        #pragma unroll
        for (int i = 0; i < 2; i++) {              // A: 512 chunks
            int c = tid * 2 + i;
            int r = c >> 2, seg = c & 3;
            CP16(s2u(&sA[st * A_EL + r * AST + seg * 8]),
                 A + (aRow0 + r) * K + kt + seg * 8);
        }
        #pragma unroll
        for (int i = 0; i < 2; i++) {              // Bh/Bl: 512 chunks each
            int c = tid * 2 + i;
            int r = c >> 4, seg = c & 15;
            CP16(s2u(&sBh[st * B_EL + r * BST + seg * 8]),
                 Bh + (size_t)(kt + r) * N + bCol0 + seg * 8);
            CP16(s2u(&sBl[st * B_EL + r * BST + seg * 8]),
                 Bl + (size_t)(kt + r) * N + bCol0 + seg * 8);
        }
    };
    load_stage(0, 0); CP_COMMIT;

    for (int it = 0; it < nk; it++) {
        if (it + 1 < nk) { load_stage((it + 1) & 1, (it + 1) * 32); CP_COMMIT; CP_WAIT(1); }
        else             { CP_WAIT(0); }
        __syncthreads();
        int st = it & 1;
        #pragma unroll
        for (int k16 = 0; k16 < 32; k16 += 16) {
            uint32_t a[4][4], bh[4][2], bl[4][2];
            #pragma unroll
            for (int mi = 0; mi < 4; mi++)
                LDSM4(a[mi], s2u(&sA[st * A_EL + (wr * 64 + mi * 16 + lrow) * AST + k16 + lseg * 8]));
            #pragma unroll
            for (int np = 0; np < 2; np++) {
                uint32_t t4[4];
                LDSM4T(t4, s2u(&sBh[st * B_EL + (k16 + lrow) * BST + wc * 32 + np * 16 + lseg * 8]));
                bh[np*2][0] = t4[0]; bh[np*2][1] = t4[1];
                bh[np*2+1][0] = t4[2]; bh[np*2+1][1] = t4[3];
                LDSM4T(t4, s2u(&sBl[st * B_EL + (k16 + lrow) * BST + wc * 32 + np * 16 + lseg * 8]));
                bl[np*2][0] = t4[0]; bl[np*2][1] = t4[1];
                bl[np*2+1][0] = t4[2]; bl[np*2+1][1] = t4[3];
            }
            #pragma unroll
            for (int mi = 0; mi < 4; mi++)
                #pragma unroll
                for (int ni = 0; ni < 4; ni++) {
                    MMA_BF16(acc[mi * 4 + ni], a[mi], bh[ni]);
                    MMA_BF16(acc[mi * 4 + ni], a[mi], bl[ni]);
                }
        }
        __syncthreads();
    }
    #pragma unroll
    for (int mi = 0; mi < 4; mi++) {
        size_t row = aRow0 + wr * 64 + mi * 16 + (lane >> 2);
        #pragma unroll
        for (int ni = 0; ni < 4; ni++) {
            int col = bCol0 + wc * 32 + ni * 8 + (lane & 3) * 2;
            float b0 = 0.f, b1 = 0.f;
            if (bias) { b0 = bias[col]; b1 = bias[col + 1]; }
            float* c = acc[mi * 4 + ni];
            float v00 = c[0] + b0, v01 = c[1] + b1;
            float v10 = c[2] + b0, v11 = c[3] + b1;
            if (Cf) {
                *(float2*)&Cf[row * N + col] = make_float2(v00, v01);
                *(float2*)&Cf[(row + 8) * N + col] = make_float2(v10, v11);
            }
            if (Cb) {
                *(__nv_bfloat162*)&Cb[row * N + col] = __floats2bfloat162_rn(v00, v01);
                *(__nv_bfloat162*)&Cb[(row + 8) * N + col] = __floats2bfloat162_rn(v10, v11);
            }
        }
    }
}

// ---------------- fused flash attention --------------------------------------
// grid (S/128, B*H), 256 threads. Q tile 128x64, KV tiles 64x64 double-buffered.
#define KST 72
#define FSMEM ((128*KST + 2*64*KST + 2*64*KST) * 2)   // 55296 bytes
__global__ void __launch_bounds__(256) flash_kernel(
    const __nv_bfloat16* __restrict__ qkvb, __nv_bfloat16* __restrict__ ob) {
    extern __shared__ __align__(16) __nv_bfloat16 fsm_[];
    __nv_bfloat16* sQ = fsm_;                  // 128 x KST
    __nv_bfloat16* sK = fsm_ + 128 * KST;      // 2 x 64 x KST
    __nv_bfloat16* sV = sK + 2 * 64 * KST;
    const int bh = blockIdx.y;
    const int b = bh >> 3, h = bh & 7;
    const int q0 = blockIdx.x * 128;
    const int tid = threadIdx.x, lane = tid & 31, warp = tid >> 5;
    const __nv_bfloat16* qb = qkvb + (size_t)(b * S_) * 1536 + h * 192;
    const __nv_bfloat16* kb = qb + 64;
    const __nv_bfloat16* vb = qb + 128;

    // load Q tile (128 rows x 64 cols): 1024 16B chunks
    #pragma unroll
    for (int i = 0; i < 4; i++) {
        int c = tid + i * 256;
        int r = c >> 3, seg = c & 7;
        CP16(s2u(&sQ[r * KST + seg * 8]), qb + (size_t)(q0 + r) * 1536 + seg * 8);
    }
    auto load_kv = [&](int buf, int t) {
        #pragma unroll
        for (int i = 0; i < 2; i++) {
            int c = tid + i * 256;
            int r = c >> 3, seg = c & 7;
            CP16(s2u(&sK[buf * 64 * KST + r * KST + seg * 8]),
                 kb + (size_t)(t * 64 + r) * 1536 + seg * 8);
            CP16(s2u(&sV[buf * 64 * KST + r * KST + seg * 8]),
                 vb + (size_t)(t * 64 + r) * 1536 + seg * 8);
        }
    };
    load_kv(0, 0); CP_COMMIT;
    CP_WAIT(0);
    __syncthreads();

    // Q fragments (held for the whole kv loop)
    uint32_t qf[4][4];
    const int qr = warp * 16;
    #pragma unroll
    for (int kk = 0; kk < 4; kk++)
        LDSM4(qf[kk], s2u(&sQ[(qr + (lane & 15)) * KST + kk * 16 + (lane >> 4) * 8]));

    float o[8][4];
    #pragma unroll
    for (int i = 0; i < 8; i++)
        #pragma unroll
        for (int j = 0; j < 4; j++) o[i][j] = 0.f;
    float m0 = -1e30f, m1 = -1e30f, l0 = 0.f, l1 = 0.f;

    const int kRow = ((lane >> 4) & 1) * 8 + (lane & 7);   // ldmatrix lane rows
    const int kCol = ((lane >> 3) & 1) * 8;
    const int vRow = ((lane >> 3) & 1) * 8 + (lane & 7);
    const int vCol = ((lane >> 4) & 1) * 8;

    for (int t = 0; t < 16; t++) {
        if (t + 1 < 16) { load_kv((t + 1) & 1, t + 1); CP_COMMIT; CP_WAIT(1); }
        else            { CP_WAIT(0); }
        __syncthreads();
        const int kbuf = (t & 1) * 64 * KST;

        // S = Q K^T
        float s[8][4];
        #pragma unroll
        for (int i = 0; i < 8; i++)
            #pragma unroll
            for (int j = 0; j < 4; j++) s[i][j] = 0.f;
        #pragma unroll
        for (int kk = 0; kk < 4; kk++) {
            uint32_t kf[8][2];
            #pragma unroll
            for (int nf2 = 0; nf2 < 4; nf2++) {
                uint32_t t4[4];
                LDSM4(t4, s2u(&sK[kbuf + (nf2 * 16 + kRow) * KST + kk * 16 + kCol]));
                kf[nf2*2][0] = t4[0]; kf[nf2*2][1] = t4[1];
                kf[nf2*2+1][0] = t4[2]; kf[nf2*2+1][1] = t4[3];
            }
            #pragma unroll
            for (int nf = 0; nf < 8; nf++)
                MMA_BF16(s[nf], qf[kk], kf[nf]);
        }

        // online softmax
        float mx0 = -1e30f, mx1 = -1e30f;
        #pragma unroll
        for (int nf = 0; nf < 8; nf++) {
            s[nf][0] *= 0.125f; s[nf][1] *= 0.125f;
            s[nf][2] *= 0.125f; s[nf][3] *= 0.125f;
            mx0 = fmaxf(mx0, fmaxf(s[nf][0], s[nf][1]));
            mx1 = fmaxf(mx1, fmaxf(s[nf][2], s[nf][3]));
        }
        mx0 = fmaxf(mx0, __shfl_xor_sync(0xffffffffu, mx0, 1));
        mx0 = fmaxf(mx0, __shfl_xor_sync(0xffffffffu, mx0, 2));
        mx1 = fmaxf(mx1, __shfl_xor_sync(0xffffffffu, mx1, 1));
        mx1 = fmaxf(mx1, __shfl_xor_sync(0xffffffffu, mx1, 2));
        float nm0 = fmaxf(m0, mx0), nm1 = fmaxf(m1, mx1);
        float sf0 = __expf(m0 - nm0), sf1 = __expf(m1 - nm1);
        m0 = nm0; m1 = nm1;
        float rs0 = 0.f, rs1 = 0.f;
        #pragma unroll
        for (int nf = 0; nf < 8; nf++) {
            s[nf][0] = __expf(s[nf][0] - nm0);
            s[nf][1] = __expf(s[nf][1] - nm0);
            s[nf][2] = __expf(s[nf][2] - nm1);
            s[nf][3] = __expf(s[nf][3] - nm1);
            rs0 += s[nf][0] + s[nf][1];
            rs1 += s[nf][2] + s[nf][3];
            o[nf][0] *= sf0; o[nf][1] *= sf0;
            o[nf][2] *= sf1; o[nf][3] *= sf1;
        }
        rs0 += __shfl_xor_sync(0xffffffffu, rs0, 1);
        rs0 += __shfl_xor_sync(0xffffffffu, rs0, 2);
        rs1 += __shfl_xor_sync(0xffffffffu, rs1, 1);
        rs1 += __shfl_xor_sync(0xffffffffu, rs1, 2);
        l0 = l0 * sf0 + rs0;
        l1 = l1 * sf1 + rs1;

        // O += P V
        #pragma unroll
        for (int kk = 0; kk < 4; kk++) {
            uint32_t pa[4];
            __nv_bfloat162 p0 = __floats2bfloat162_rn(s[2*kk][0], s[2*kk][1]);
            __nv_bfloat162 p1 = __floats2bfloat162_rn(s[2*kk][2], s[2*kk][3]);
            __nv_bfloat162 p2 = __floats2bfloat162_rn(s[2*kk+1][0], s[2*kk+1][1]);
            __nv_bfloat162 p3 = __floats2bfloat162_rn(s[2*kk+1][2], s[2*kk+1][3]);
            pa[0] = *(uint32_t*)&p0; pa[1] = *(uint32_t*)&p1;
            pa[2] = *(uint32_t*)&p2; pa[3] = *(uint32_t*)&p3;
            uint32_t vf[8][2];
            #pragma unroll
            for (int nf2 = 0; nf2 < 4; nf2++) {
                uint32_t t4[4];
                LDSM4T(t4, s2u(&sV[kbuf + (kk * 16 + vRow) * KST + nf2 * 16 + vCol]));
                vf[nf2*2][0] = t4[0]; vf[nf2*2][1] = t4[1];
                vf[nf2*2+1][0] = t4[2]; vf[nf2*2+1][1] = t4[3];
            }
            #pragma unroll
            for (int nf = 0; nf < 8; nf++)
                MMA_BF16(o[nf], pa, vf[nf]);
        }
        __syncthreads();
    }

    // epilogue: normalize, write bf16
    float inv0 = 1.f / l0, inv1 = 1.f / l1;
    size_t r0 = (size_t)b * S_ + q0 + qr + (lane >> 2);
    size_t r1 = r0 + 8;
    #pragma unroll
    for (int nf = 0; nf < 8; nf++) {
        int col = h * 64 + nf * 8 + (lane & 3) * 2;
        *(__nv_bfloat162*)&ob[r0 * D_ + col] =
            __floats2bfloat162_rn(o[nf][0] * inv0, o[nf][1] * inv0);
        *(__nv_bfloat162*)&ob[r1 * D_ + col] =
            __floats2bfloat162_rn(o[nf][2] * inv1, o[nf][3] * inv1);
    }
}

// ---------------- embedding + sinusoidal PE ----------------------------------
__global__ void __launch_bounds__(256) embed_kernel(const int* __restrict__ tokens,
                                                    const float* __restrict__ emb) {
    int idx = blockIdx.x * 256 + threadIdx.x;
    int d = idx & (D_ - 1);
    int bs = idx >> 9;
    int s = bs & (S_ - 1);
    int tok = tokens[bs];
    float div = expf((float)(d & ~1) * (-9.210340371976184f / (float)D_));
    float ang = (float)s * div;
    float pe = (d & 1) ? cosf(ang) : sinf(ang);
    float v = emb[(size_t)tok * D_ + d] + pe;
    g_x[idx] = v;
    g_xb[idx] = __float2bfloat16(v);
}

// ---------------- residual + bias + LayerNorm --------------------------------
__global__ void __launch_bounds__(128) ln_kernel(const float* __restrict__ bias,
                                                 const float* __restrict__ gamma,
                                                 const float* __restrict__ beta) {
    size_t r = blockIdx.x;
    int tid = threadIdx.x;
    float4 o = *(float4*)(g_p + r * D_ + tid * 4);
    float4 xr = *(float4*)(g_x + r * D_ + tid * 4);
    float4 bb = *(const float4*)(bias + tid * 4);
    float4 y;
    y.x = o.x + xr.x + bb.x; y.y = o.y + xr.y + bb.y;
    y.z = o.z + xr.z + bb.z; y.w = o.w + xr.w + bb.w;
    __shared__ float sm[4], ss[4];
    float s = y.x + y.y + y.z + y.w;
    #pragma unroll
    for (int o2 = 16; o2; o2 >>= 1) s += __shfl_xor_sync(0xffffffffu, s, o2);
    if ((tid & 31) == 0) sm[tid >> 5] = s;
    __syncthreads();
    float mean = (sm[0] + sm[1] + sm[2] + sm[3]) * (1.0f / D_);
    float dx = y.x - mean, dy = y.y - mean, dz = y.z - mean, dw = y.w - mean;
    float sq = dx*dx + dy*dy + dz*dz + dw*dw;
    #pragma unroll
    for (int o2 = 16; o2; o2 >>= 1) sq += __shfl_xor_sync(0xffffffffu, sq, o2);
    if ((tid & 31) == 0) ss[tid >> 5] = sq;
    __syncthreads();
    float var = (ss[0] + ss[1] + ss[2] + ss[3]) * (1.0f / D_);
    float inv = rsqrtf(var + 1e-5f);
    float4 g = *(const float4*)(gamma + tid * 4);
    float4 be = *(const float4*)(beta + tid * 4);
    float4 out;
    out.x = dx * inv * g.x + be.x; out.y = dy * inv * g.y + be.y;
    out.z = dz * inv * g.z + be.z; out.w = dw * inv * g.w + be.w;
    *(float4*)(g_x + r * D_ + tid * 4) = out;
    *(__nv_bfloat162*)&g_xb[r * D_ + tid * 4]     = __floats2bfloat162_rn(out.x, out.y);
    *(__nv_bfloat162*)&g_xb[r * D_ + tid * 4 + 2] = __floats2bfloat162_rn(out.z, out.w);
}

// ---------------- mean pool / MLP ---------------------------------------------
__global__ void __launch_bounds__(512) pool_kernel() {
    int b = blockIdx.x, d = threadIdx.x;
    const float* base = g_x + (size_t)b * S_ * D_ + d;
    float s = 0.f;
    for (int i = 0; i < S_; i++) s += base[(size_t)i * D_];
    g_pool[b * D_ + d] = s * (1.0f / S_);
}

__global__ void __launch_bounds__(256) mlp1_kernel(const float* __restrict__ w,
                                                   const float* __restrict__ bias) {
    int f = blockIdx.x * 256 + threadIdx.x;
    int b = blockIdx.y;
    float acc = bias[f];
    const float* pr = g_pool + b * D_;
    for (int d = 0; d < D_; d++) acc = fmaf(pr[d], w[(size_t)d * FF_ + f], acc);
    g_h1[b * FF_ + f] = fmaxf(acc, 0.f);
}

__global__ void __launch_bounds__(192) mlp2_kernel(const float* __restrict__ w,
                                                   const float* __restrict__ bias,
                                                   float* __restrict__ out) {
    int t = threadIdx.x;
    int b = t / C_, c = t % C_;
    float acc = bias[c];
    const float* hr = g_h1 + b * FF_;
    for (int f = 0; f < FF_; f++) acc = fmaf(hr[f], w[f * C_ + c], acc);
    out[b * C_ + c] = acc;
}

// ---------------- launch ------------------------------------------------------
extern "C" void kernel_launch(void* const* d_in, const int* in_sizes, int n_in,
                              void* d_out, int out_size) {
    const int*   tokens = (const int*)d_in[0];
    const float* emb    = (const float*)d_in[1];
    const float* qkv_w  = (const float*)d_in[2];
    const float* qkv_b  = (const float*)d_in[3];
    const float* fc_w   = (const float*)d_in[4];
    const float* fc_b   = (const float*)d_in[5];
    const float* gamma  = (const float*)d_in[6];
    const float* beta   = (const float*)d_in[7];
    const float* fc1_w  = (const float*)d_in[8];
    const float* fc1_b  = (const float*)d_in[9];
    const float* fc2_w  = (const float*)d_in[10];
    const float* fc2_b  = (const float*)d_in[11];
    float* out = (float*)d_out;
    (void)in_sizes; (void)n_in; (void)out_size;

    cudaFuncSetAttribute(gemm_bf16x2, cudaFuncAttributeMaxDynamicSharedMemorySize, GSMEM);
    cudaFuncSetAttribute(flash_kernel, cudaFuncAttributeMaxDynamicSharedMemorySize, FSMEM);

    __nv_bfloat16 *xb, *qkvb, *obf;
    float *p;
    uint16_t *wh, *wl;
    cudaGetSymbolAddress((void**)&xb,   g_xb);
    cudaGetSymbolAddress((void**)&qkvb, g_qkvb);
    cudaGetSymbolAddress((void**)&obf,  g_ob);
    cudaGetSymbolAddress((void**)&p,    g_p);
    cudaGetSymbolAddress((void**)&wh,   g_wh);
    cudaGetSymbolAddress((void**)&wl,   g_wl);

    embed_kernel<<<(BS_ * D_) / 256, 256>>>(tokens, emb);

    for (int l = 0; l < L_; l++) {
        // QKV: bf16 out for flash
        convert_hl<<<(D_ * 3 * D_) / 1024, 256>>>(qkv_w + (size_t)l * D_ * 3 * D_, wh, wl);
        gemm_bf16x2<<<dim3(3 * D_ / 128, BS_ / 128), 256, GSMEM>>>(
            xb, wh, wl, qkv_b + (size_t)l * 3 * D_,
            (float*)nullptr, qkvb, 3 * D_, D_);
        // fused attention
        flash_kernel<<<dim3(S_ / 128, B_ * H_), 256, FSMEM>>>(qkvb, obf);
        // projection (bias folded into LN)
        convert_hl<<<(D_ * D_) / 1024, 256>>>(fc_w + (size_t)l * D_ * D_, wh, wl);
        gemm_bf16x2<<<dim3(D_ / 128, BS_ / 128), 256, GSMEM>>>(
            obf, wh, wl, (const float*)nullptr,
            p, (__nv_bfloat16*)nullptr, D_, D_);
        // x = LN(p + fc_b[l] + x), writes fp32 + bf16
        ln_kernel<<<BS_, 128>>>(fc_b + (size_t)l * D_, gamma, beta);
    }

    pool_kernel<<<B_, 512>>>();
    mlp1_kernel<<<dim3(FF_ / 256, B_), 256>>>(fc1_w, fc1_b);
    mlp2_kernel<<<1, B_ * C_>>>(fc2_w, fc2_b, out);
}

// round 6
// speedup vs baseline: 8.8585x; 1.0344x over previous
#include <cuda_runtime.h>
#include <cuda_bf16.h>
#include <math.h>
#include <stdint.h>

#define B_ 32
#define S_ 1024
#define D_ 512
#define H_ 8
#define L_ 3
#define FF_ 2048
#define C_ 6
#define BS_ (B_*S_)

// ---------------- scratch (device globals) ----------------------------------
static __device__ float          g_x[(size_t)BS_*D_];        // residual fp32
static __device__ __nv_bfloat16  g_xb[(size_t)BS_*D_];       // residual bf16
static __device__ __nv_bfloat16  g_qkvb[(size_t)BS_*3*D_];   // qkv bf16 (q pre-scaled)
static __device__ __nv_bfloat16  g_ob[(size_t)BS_*D_];       // attn out bf16
static __device__ float          g_p[(size_t)BS_*D_];        // proj out fp32
static __device__ float          g_pool[B_*D_];
static __device__ float          g_h1[B_*FF_];
static __device__ uint16_t       g_wh[(size_t)D_*3*D_];      // weight hi
static __device__ uint16_t       g_wl[(size_t)D_*3*D_];      // weight lo

// ---------------- asm helpers ------------------------------------------------
__device__ __forceinline__ uint32_t s2u(const void* p) {
    return (uint32_t)__cvta_generic_to_shared(p);
}
#define LDSM4(R, addr) \
    asm volatile("ldmatrix.sync.aligned.m8n8.x4.shared.b16 {%0,%1,%2,%3}, [%4];" \
        : "=r"((R)[0]), "=r"((R)[1]), "=r"((R)[2]), "=r"((R)[3]) : "r"(addr))
#define LDSM4T(R, addr) \
    asm volatile("ldmatrix.sync.aligned.m8n8.x4.trans.shared.b16 {%0,%1,%2,%3}, [%4];" \
        : "=r"((R)[0]), "=r"((R)[1]), "=r"((R)[2]), "=r"((R)[3]) : "r"(addr))
#define MMA_BF16(c, a, b) \
    asm volatile("mma.sync.aligned.m16n8k16.row.col.f32.bf16.bf16.f32 " \
        "{%0,%1,%2,%3},{%4,%5,%6,%7},{%8,%9},{%0,%1,%2,%3};" \
        : "+f"((c)[0]), "+f"((c)[1]), "+f"((c)[2]), "+f"((c)[3]) \
        : "r"((a)[0]), "r"((a)[1]), "r"((a)[2]), "r"((a)[3]), "r"((b)[0]), "r"((b)[1]))
#define CP16(dst, src) \
    asm volatile("cp.async.cg.shared.global [%0], [%1], 16;" :: "r"(dst), "l"(src))
#define CP_COMMIT asm volatile("cp.async.commit_group;")
#define CP_WAIT(n) asm volatile("cp.async.wait_group %0;" :: "n"(n))

// ---------------- fp32 -> bf16 hi/lo split (weights) -------------------------
__global__ void __launch_bounds__(256) convert_hl(const float* __restrict__ in,
                                                  uint16_t* __restrict__ hi,
                                                  uint16_t* __restrict__ lo) {
    int i = blockIdx.x * 256 + threadIdx.x;
    float4 v = ((const float4*)in)[i];
    float f[4] = {v.x, v.y, v.z, v.w};
    ushort4 ph, pl;
    unsigned short* hh = (unsigned short*)&ph;
    unsigned short* ll = (unsigned short*)&pl;
    #pragma unroll
    for (int j = 0; j < 4; j++) {
        __nv_bfloat16 h = __float2bfloat16(f[j]);
        float hf = __bfloat162float(h);
        __nv_bfloat16 l = __float2bfloat16(f[j] - hf);
        hh[j] = *(unsigned short*)&h;
        ll[j] = *(unsigned short*)&l;
    }
    ((ushort4*)hi)[i] = ph;
    ((ushort4*)lo)[i] = pl;
}

// ---------------- pipelined bf16x2 GEMM --------------------------------------
// C = A(bf16)[M,K] @ (Wh+Wl)[K,N] + bias. 128x128 tile, cp.async double buffer.
// qscale: scale Q columns (col%192 < 64) by 0.125 in bf16 epilogue.
#define AST 40
#define BST 136
#define A_EL (128*AST)
#define B_EL (32*BST)
#define GSMEM ((2*A_EL + 4*B_EL) * 2)   // 55296 bytes
__global__ void __launch_bounds__(256, 2) gemm_bf16x2(
    const __nv_bfloat16* __restrict__ A,
    const uint16_t* __restrict__ Bh, const uint16_t* __restrict__ Bl,
    const float* __restrict__ bias,
    float* __restrict__ Cf, __nv_bfloat16* __restrict__ Cb, int N, int K,
    int qscale) {
    extern __shared__ __align__(16) uint16_t sm_[];
    uint16_t* sA  = sm_;
    uint16_t* sBh = sm_ + 2 * A_EL;
    uint16_t* sBl = sBh + 2 * B_EL;
    const int tid = threadIdx.x;
    const int lane = tid & 31, warp = tid >> 5;
    const int wr = warp >> 2, wc = warp & 3;
    const size_t aRow0 = (size_t)blockIdx.y * 128;
    const int bCol0 = blockIdx.x * 128;
    const int lrow = lane & 15, lseg = lane >> 4;

    float acc[16][4];
    #pragma unroll
    for (int i = 0; i < 16; i++)
        #pragma unroll
        for (int j = 0; j < 4; j++) acc[i][j] = 0.f;

    const int nk = K / 32;
    auto load_stage = [&](int st, int kt) {
        #pragma unroll
        for (int i = 0; i < 2; i++) {
            int c = tid * 2 + i;
            int r = c >> 2, seg = c & 3;
            CP16(s2u(&sA[st * A_EL + r * AST + seg * 8]),
                 A + (aRow0 + r) * K + kt + seg * 8);
        }
        #pragma unroll
        for (int i = 0; i < 2; i++) {
            int c = tid * 2 + i;
            int r = c >> 4, seg = c & 15;
            CP16(s2u(&sBh[st * B_EL + r * BST + seg * 8]),
                 Bh + (size_t)(kt + r) * N + bCol0 + seg * 8);
            CP16(s2u(&sBl[st * B_EL + r * BST + seg * 8]),
                 Bl + (size_t)(kt + r) * N + bCol0 + seg * 8);
        }
    };
    load_stage(0, 0); CP_COMMIT;

    for (int it = 0; it < nk; it++) {
        if (it + 1 < nk) { load_stage((it + 1) & 1, (it + 1) * 32); CP_COMMIT; CP_WAIT(1); }
        else             { CP_WAIT(0); }
        __syncthreads();
        int st = it & 1;
        #pragma unroll
        for (int k16 = 0; k16 < 32; k16 += 16) {
            uint32_t a[4][4], bh[4][2], bl[4][2];
            #pragma unroll
            for (int mi = 0; mi < 4; mi++)
                LDSM4(a[mi], s2u(&sA[st * A_EL + (wr * 64 + mi * 16 + lrow) * AST + k16 + lseg * 8]));
            #pragma unroll
            for (int np = 0; np < 2; np++) {
                uint32_t t4[4];
                LDSM4T(t4, s2u(&sBh[st * B_EL + (k16 + lrow) * BST + wc * 32 + np * 16 + lseg * 8]));
                bh[np*2][0] = t4[0]; bh[np*2][1] = t4[1];
                bh[np*2+1][0] = t4[2]; bh[np*2+1][1] = t4[3];
                LDSM4T(t4, s2u(&sBl[st * B_EL + (k16 + lrow) * BST + wc * 32 + np * 16 + lseg * 8]));
                bl[np*2][0] = t4[0]; bl[np*2][1] = t4[1];
                bl[np*2+1][0] = t4[2]; bl[np*2+1][1] = t4[3];
            }
            #pragma unroll
            for (int mi = 0; mi < 4; mi++)
                #pragma unroll
                for (int ni = 0; ni < 4; ni++) {
                    MMA_BF16(acc[mi * 4 + ni], a[mi], bh[ni]);
                    MMA_BF16(acc[mi * 4 + ni], a[mi], bl[ni]);
                }
        }
        __syncthreads();
    }
    #pragma unroll
    for (int mi = 0; mi < 4; mi++) {
        size_t row = aRow0 + wr * 64 + mi * 16 + (lane >> 2);
        #pragma unroll
        for (int ni = 0; ni < 4; ni++) {
            int col = bCol0 + wc * 32 + ni * 8 + (lane & 3) * 2;
            float b0 = 0.f, b1 = 0.f;
            if (bias) { b0 = bias[col]; b1 = bias[col + 1]; }
            float* c = acc[mi * 4 + ni];
            float v00 = c[0] + b0, v01 = c[1] + b1;
            float v10 = c[2] + b0, v11 = c[3] + b1;
            if (Cf) {
                *(float2*)&Cf[row * N + col] = make_float2(v00, v01);
                *(float2*)&Cf[(row + 8) * N + col] = make_float2(v10, v11);
            }
            if (Cb) {
                float sc = (qscale && ((col % 192) < 64)) ? 0.125f : 1.0f;
                *(__nv_bfloat162*)&Cb[row * N + col] =
                    __floats2bfloat162_rn(v00 * sc, v01 * sc);
                *(__nv_bfloat162*)&Cb[(row + 8) * N + col] =
                    __floats2bfloat162_rn(v10 * sc, v11 * sc);
            }
        }
    }
}

// ---------------- fused flash attention (no-max softmax) ---------------------
// grid (S/128, B*H), 256 threads. Q 128x64 (pre-scaled by 1/8), KV 64x64 x2buf.
#define KST 72
#define FSMEM ((128*KST + 2*64*KST + 2*64*KST) * 2)
__global__ void __launch_bounds__(256) flash_kernel(
    const __nv_bfloat16* __restrict__ qkvb, __nv_bfloat16* __restrict__ ob) {
    extern __shared__ __align__(16) __nv_bfloat16 fsm_[];
    __nv_bfloat16* sQ = fsm_;
    __nv_bfloat16* sK = fsm_ + 128 * KST;
    __nv_bfloat16* sV = sK + 2 * 64 * KST;
    const int bh = blockIdx.y;
    const int b = bh >> 3, h = bh & 7;
    const int q0 = blockIdx.x * 128;
    const int tid = threadIdx.x, lane = tid & 31, warp = tid >> 5;
    const __nv_bfloat16* qb = qkvb + (size_t)(b * S_) * 1536 + h * 192;
    const __nv_bfloat16* kb = qb + 64;
    const __nv_bfloat16* vb = qb + 128;

    #pragma unroll
    for (int i = 0; i < 4; i++) {
        int c = tid + i * 256;
        int r = c >> 3, seg = c & 7;
        CP16(s2u(&sQ[r * KST + seg * 8]), qb + (size_t)(q0 + r) * 1536 + seg * 8);
    }
    auto load_kv = [&](int buf, int t) {
        #pragma unroll
        for (int i = 0; i < 2; i++) {
            int c = tid + i * 256;
            int r = c >> 3, seg = c & 7;
            CP16(s2u(&sK[buf * 64 * KST + r * KST + seg * 8]),
                 kb + (size_t)(t * 64 + r) * 1536 + seg * 8);
            CP16(s2u(&sV[buf * 64 * KST + r * KST + seg * 8]),
                 vb + (size_t)(t * 64 + r) * 1536 + seg * 8);
        }
    };
    load_kv(0, 0); CP_COMMIT;
    CP_WAIT(0);
    __syncthreads();

    uint32_t qf[4][4];
    const int qr = warp * 16;
    #pragma unroll
    for (int kk = 0; kk < 4; kk++)
        LDSM4(qf[kk], s2u(&sQ[(qr + (lane & 15)) * KST + kk * 16 + (lane >> 4) * 8]));

    float o[8][4];
    #pragma unroll
    for (int i = 0; i < 8; i++)
        #pragma unroll
        for (int j = 0; j < 4; j++) o[i][j] = 0.f;
    float l0 = 0.f, l1 = 0.f;     // running exp-sums (no max shift; logits bounded)

    const int kRow = ((lane >> 4) & 1) * 8 + (lane & 7);
    const int kCol = ((lane >> 3) & 1) * 8;
    const int vRow = ((lane >> 3) & 1) * 8 + (lane & 7);
    const int vCol = ((lane >> 4) & 1) * 8;

    for (int t = 0; t < 16; t++) {
        if (t + 1 < 16) { load_kv((t + 1) & 1, t + 1); CP_COMMIT; CP_WAIT(1); }
        else            { CP_WAIT(0); }
        __syncthreads();
        const int kbuf = (t & 1) * 64 * KST;

        // S = Q K^T  (Q already scaled by 1/8)
        float s[8][4];
        #pragma unroll
        for (int i = 0; i < 8; i++)
            #pragma unroll
            for (int j = 0; j < 4; j++) s[i][j] = 0.f;
        #pragma unroll
        for (int kk = 0; kk < 4; kk++) {
            uint32_t kf[8][2];
            #pragma unroll
            for (int nf2 = 0; nf2 < 4; nf2++) {
                uint32_t t4[4];
                LDSM4(t4, s2u(&sK[kbuf + (nf2 * 16 + kRow) * KST + kk * 16 + kCol]));
                kf[nf2*2][0] = t4[0]; kf[nf2*2][1] = t4[1];
                kf[nf2*2+1][0] = t4[2]; kf[nf2*2+1][1] = t4[3];
            }
            #pragma unroll
            for (int nf = 0; nf < 8; nf++)
                MMA_BF16(s[nf], qf[kk], kf[nf]);
        }

        // P = exp(S); accumulate row sums (shift-free softmax)
        float rs0 = 0.f, rs1 = 0.f;
        #pragma unroll
        for (int nf = 0; nf < 8; nf++) {
            s[nf][0] = __expf(s[nf][0]);
            s[nf][1] = __expf(s[nf][1]);
            s[nf][2] = __expf(s[nf][2]);
            s[nf][3] = __expf(s[nf][3]);
            rs0 += s[nf][0] + s[nf][1];
            rs1 += s[nf][2] + s[nf][3];
        }
        rs0 += __shfl_xor_sync(0xffffffffu, rs0, 1);
        rs0 += __shfl_xor_sync(0xffffffffu, rs0, 2);
        rs1 += __shfl_xor_sync(0xffffffffu, rs1, 1);
        rs1 += __shfl_xor_sync(0xffffffffu, rs1, 2);
        l0 += rs0;
        l1 += rs1;

        // O += P V
        #pragma unroll
        for (int kk = 0; kk < 4; kk++) {
            uint32_t pa[4];
            __nv_bfloat162 p0 = __floats2bfloat162_rn(s[2*kk][0], s[2*kk][1]);
            __nv_bfloat162 p1 = __floats2bfloat162_rn(s[2*kk][2], s[2*kk][3]);
            __nv_bfloat162 p2 = __floats2bfloat162_rn(s[2*kk+1][0], s[2*kk+1][1]);
            __nv_bfloat162 p3 = __floats2bfloat162_rn(s[2*kk+1][2], s[2*kk+1][3]);
            pa[0] = *(uint32_t*)&p0; pa[1] = *(uint32_t*)&p1;
            pa[2] = *(uint32_t*)&p2; pa[3] = *(uint32_t*)&p3;
            uint32_t vf[8][2];
            #pragma unroll
            for (int nf2 = 0; nf2 < 4; nf2++) {
                uint32_t t4[4];
                LDSM4T(t4, s2u(&sV[kbuf + (kk * 16 + vRow) * KST + nf2 * 16 + vCol]));
                vf[nf2*2][0] = t4[0]; vf[nf2*2][1] = t4[1];
                vf[nf2*2+1][0] = t4[2]; vf[nf2*2+1][1] = t4[3];
            }
            #pragma unroll
            for (int nf = 0; nf < 8; nf++)
                MMA_BF16(o[nf], pa, vf[nf]);
        }
        __syncthreads();
    }

    float inv0 = 1.f / l0, inv1 = 1.f / l1;
    size_t r0 = (size_t)b * S_ + q0 + qr + (lane >> 2);
    size_t r1 = r0 + 8;
    #pragma unroll
    for (int nf = 0; nf < 8; nf++) {
        int col = h * 64 + nf * 8 + (lane & 3) * 2;
        *(__nv_bfloat162*)&ob[r0 * D_ + col] =
            __floats2bfloat162_rn(o[nf][0] * inv0, o[nf][1] * inv0);
        *(__nv_bfloat162*)&ob[r1 * D_ + col] =
            __floats2bfloat162_rn(o[nf][2] * inv1, o[nf][3] * inv1);
    }
}

// ---------------- embedding + sinusoidal PE ----------------------------------
__global__ void __launch_bounds__(256) embed_kernel(const int* __restrict__ tokens,
                                                    const float* __restrict__ emb) {
    int idx = blockIdx.x * 256 + threadIdx.x;
    int d = idx & (D_ - 1);
    int bs = idx >> 9;
    int s = bs & (S_ - 1);
    int tok = tokens[bs];
    float div = expf((float)(d & ~1) * (-9.210340371976184f / (float)D_));
    float ang = (float)s * div;
    float pe = (d & 1) ? cosf(ang) : sinf(ang);
    float v = emb[(size_t)tok * D_ + d] + pe;
    g_x[idx] = v;
    g_xb[idx] = __float2bfloat16(v);
}

// ---------------- residual + bias + LayerNorm --------------------------------
__global__ void __launch_bounds__(128) ln_kernel(const float* __restrict__ bias,
                                                 const float* __restrict__ gamma,
                                                 const float* __restrict__ beta) {
    size_t r = blockIdx.x;
    int tid = threadIdx.x;
    float4 o = *(float4*)(g_p + r * D_ + tid * 4);
    float4 xr = *(float4*)(g_x + r * D_ + tid * 4);
    float4 bb = *(const float4*)(bias + tid * 4);
    float4 y;
    y.x = o.x + xr.x + bb.x; y.y = o.y + xr.y + bb.y;
    y.z = o.z + xr.z + bb.z; y.w = o.w + xr.w + bb.w;
    __shared__ float sm[4], ss[4];
    float s = y.x + y.y + y.z + y.w;
    #pragma unroll
    for (int o2 = 16; o2; o2 >>= 1) s += __shfl_xor_sync(0xffffffffu, s, o2);
    if ((tid & 31) == 0) sm[tid >> 5] = s;
    __syncthreads();
    float mean = (sm[0] + sm[1] + sm[2] + sm[3]) * (1.0f / D_);
    float dx = y.x - mean, dy = y.y - mean, dz = y.z - mean, dw = y.w - mean;
    float sq = dx*dx + dy*dy + dz*dz + dw*dw;
    #pragma unroll
    for (int o2 = 16; o2; o2 >>= 1) sq += __shfl_xor_sync(0xffffffffu, sq, o2);
    if ((tid & 31) == 0) ss[tid >> 5] = sq;
    __syncthreads();
    float var = (ss[0] + ss[1] + ss[2] + ss[3]) * (1.0f / D_);
    float inv = rsqrtf(var + 1e-5f);
    float4 g = *(const float4*)(gamma + tid * 4);
    float4 be = *(const float4*)(beta + tid * 4);
    float4 out;
    out.x = dx * inv * g.x + be.x; out.y = dy * inv * g.y + be.y;
    out.z = dz * inv * g.z + be.z; out.w = dw * inv * g.w + be.w;
    *(float4*)(g_x + r * D_ + tid * 4) = out;
    *(__nv_bfloat162*)&g_xb[r * D_ + tid * 4]     = __floats2bfloat162_rn(out.x, out.y);
    *(__nv_bfloat162*)&g_xb[r * D_ + tid * 4 + 2] = __floats2bfloat162_rn(out.z, out.w);
}

// ---------------- mean pool / MLP ---------------------------------------------
__global__ void __launch_bounds__(512) pool_kernel() {
    int b = blockIdx.x, d = threadIdx.x;
    const float* base = g_x + (size_t)b * S_ * D_ + d;
    float s = 0.f;
    for (int i = 0; i < S_; i++) s += base[(size_t)i * D_];
    g_pool[b * D_ + d] = s * (1.0f / S_);
}

__global__ void __launch_bounds__(256) mlp1_kernel(const float* __restrict__ w,
                                                   const float* __restrict__ bias) {
    int f = blockIdx.x * 256 + threadIdx.x;
    int b = blockIdx.y;
    float acc = bias[f];
    const float* pr = g_pool + b * D_;
    for (int d = 0; d < D_; d++) acc = fmaf(pr[d], w[(size_t)d * FF_ + f], acc);
    g_h1[b * FF_ + f] = fmaxf(acc, 0.f);
}

__global__ void __launch_bounds__(192) mlp2_kernel(const float* __restrict__ w,
                                                   const float* __restrict__ bias,
                                                   float* __restrict__ out) {
    int t = threadIdx.x;
    int b = t / C_, c = t % C_;
    float acc = bias[c];
    const float* hr = g_h1 + b * FF_;
    for (int f = 0; f < FF_; f++) acc = fmaf(hr[f], w[f * C_ + c], acc);
    out[b * C_ + c] = acc;
}

// ---------------- launch ------------------------------------------------------
extern "C" void kernel_launch(void* const* d_in, const int* in_sizes, int n_in,
                              void* d_out, int out_size) {
    const int*   tokens = (const int*)d_in[0];
    const float* emb    = (const float*)d_in[1];
    const float* qkv_w  = (const float*)d_in[2];
    const float* qkv_b  = (const float*)d_in[3];
    const float* fc_w   = (const float*)d_in[4];
    const float* fc_b   = (const float*)d_in[5];
    const float* gamma  = (const float*)d_in[6];
    const float* beta   = (const float*)d_in[7];
    const float* fc1_w  = (const float*)d_in[8];
    const float* fc1_b  = (const float*)d_in[9];
    const float* fc2_w  = (const float*)d_in[10];
    const float* fc2_b  = (const float*)d_in[11];
    float* out = (float*)d_out;
    (void)in_sizes; (void)n_in; (void)out_size;

    cudaFuncSetAttribute(gemm_bf16x2, cudaFuncAttributeMaxDynamicSharedMemorySize, GSMEM);
    cudaFuncSetAttribute(flash_kernel, cudaFuncAttributeMaxDynamicSharedMemorySize, FSMEM);

    __nv_bfloat16 *xb, *qkvb, *obf;
    float *p;
    uint16_t *wh, *wl;
    cudaGetSymbolAddress((void**)&xb,   g_xb);
    cudaGetSymbolAddress((void**)&qkvb, g_qkvb);
    cudaGetSymbolAddress((void**)&obf,  g_ob);
    cudaGetSymbolAddress((void**)&p,    g_p);
    cudaGetSymbolAddress((void**)&wh,   g_wh);
    cudaGetSymbolAddress((void**)&wl,   g_wl);

    embed_kernel<<<(BS_ * D_) / 256, 256>>>(tokens, emb);

    for (int l = 0; l < L_; l++) {
        // QKV: bf16 out, Q columns pre-scaled by 1/8
        convert_hl<<<(D_ * 3 * D_) / 1024, 256>>>(qkv_w + (size_t)l * D_ * 3 * D_, wh, wl);
        gemm_bf16x2<<<dim3(3 * D_ / 128, BS_ / 128), 256, GSMEM>>>(
            xb, wh, wl, qkv_b + (size_t)l * 3 * D_,
            (float*)nullptr, qkvb, 3 * D_, D_, 1);
        // fused attention
        flash_kernel<<<dim3(S_ / 128, B_ * H_), 256, FSMEM>>>(qkvb, obf);
        // projection (bias folded into LN)
        convert_hl<<<(D_ * D_) / 1024, 256>>>(fc_w + (size_t)l * D_ * D_, wh, wl);
        gemm_bf16x2<<<dim3(D_ / 128, BS_ / 128), 256, GSMEM>>>(
            obf, wh, wl, (const float*)nullptr,
            p, (__nv_bfloat16*)nullptr, D_, D_, 0);
        // x = LN(p + fc_b + x)
        ln_kernel<<<BS_, 128>>>(fc_b + (size_t)l * D_, gamma, beta);
    }

    pool_kernel<<<B_, 512>>>();
    mlp1_kernel<<<dim3(FF_ / 256, B_), 256>>>(fc1_w, fc1_b);
    mlp2_kernel<<<1, B_ * C_>>>(fc2_w, fc2_b, out);
}

// round 7
// speedup vs baseline: 9.3177x; 1.0518x over previous
#include <cuda_runtime.h>
#include <cuda_bf16.h>
#include <math.h>
#include <stdint.h>

#define B_ 32
#define S_ 1024
#define D_ 512
#define H_ 8
#define L_ 3
#define FF_ 2048
#define C_ 6
#define BS_ (B_*S_)

// ---------------- scratch (device globals) ----------------------------------
static __device__ float          g_x[(size_t)BS_*D_];        // residual fp32
static __device__ __nv_bfloat16  g_xb[(size_t)BS_*D_];       // residual bf16
static __device__ __nv_bfloat16  g_qkvb[(size_t)BS_*3*D_];   // qkv bf16 (q pre-scaled)
static __device__ __nv_bfloat16  g_ob[(size_t)BS_*D_];       // attn out bf16
static __device__ float          g_p[(size_t)BS_*D_];        // proj out fp32
static __device__ float          g_pool[B_*D_];
static __device__ float          g_h1[B_*FF_];
// all layers' weights, hi/lo: [0, 3*786432) qkv per layer, then fc at +l*262144
#define WQKV_OFF(l) ((size_t)(l) * (size_t)(D_*3*D_))
#define WFC_OFF(l)  ((size_t)3 * (D_*3*D_) + (size_t)(l) * (D_*D_))
#define WTOT ((size_t)3 * (D_*3*D_) + (size_t)3 * (D_*D_))
static __device__ uint16_t       g_wh[WTOT];
static __device__ uint16_t       g_wl[WTOT];

// ---------------- asm helpers ------------------------------------------------
__device__ __forceinline__ uint32_t s2u(const void* p) {
    return (uint32_t)__cvta_generic_to_shared(p);
}
#define LDSM4(R, addr) \
    asm volatile("ldmatrix.sync.aligned.m8n8.x4.shared.b16 {%0,%1,%2,%3}, [%4];" \
        : "=r"((R)[0]), "=r"((R)[1]), "=r"((R)[2]), "=r"((R)[3]) : "r"(addr))
#define LDSM4T(R, addr) \
    asm volatile("ldmatrix.sync.aligned.m8n8.x4.trans.shared.b16 {%0,%1,%2,%3}, [%4];" \
        : "=r"((R)[0]), "=r"((R)[1]), "=r"((R)[2]), "=r"((R)[3]) : "r"(addr))
#define MMA_BF16(c, a, b) \
    asm volatile("mma.sync.aligned.m16n8k16.row.col.f32.bf16.bf16.f32 " \
        "{%0,%1,%2,%3},{%4,%5,%6,%7},{%8,%9},{%0,%1,%2,%3};" \
        : "+f"((c)[0]), "+f"((c)[1]), "+f"((c)[2]), "+f"((c)[3]) \
        : "r"((a)[0]), "r"((a)[1]), "r"((a)[2]), "r"((a)[3]), "r"((b)[0]), "r"((b)[1]))
#define CP16(dst, src) \
    asm volatile("cp.async.cg.shared.global [%0], [%1], 16;" :: "r"(dst), "l"(src))
#define CP_COMMIT asm volatile("cp.async.commit_group;")
#define CP_WAIT(n) asm volatile("cp.async.wait_group %0;" :: "n"(n))
__device__ __forceinline__ float ex2f(float x) {
    float y;
    asm("ex2.approx.f32 %0, %1;" : "=f"(y) : "f"(x));
    return y;
}

// ---------------- fp32 -> bf16 hi/lo split (weights) -------------------------
__global__ void __launch_bounds__(256) convert_hl(const float* __restrict__ in,
                                                  uint16_t* __restrict__ hi,
                                                  uint16_t* __restrict__ lo) {
    int i = blockIdx.x * 256 + threadIdx.x;
    float4 v = ((const float4*)in)[i];
    float f[4] = {v.x, v.y, v.z, v.w};
    ushort4 ph, pl;
    unsigned short* hh = (unsigned short*)&ph;
    unsigned short* ll = (unsigned short*)&pl;
    #pragma unroll
    for (int j = 0; j < 4; j++) {
        __nv_bfloat16 h = __float2bfloat16(f[j]);
        float hf = __bfloat162float(h);
        __nv_bfloat16 l = __float2bfloat16(f[j] - hf);
        hh[j] = *(unsigned short*)&h;
        ll[j] = *(unsigned short*)&l;
    }
    ((ushort4*)hi)[i] = ph;
    ((ushort4*)lo)[i] = pl;
}

// ---------------- pipelined bf16x2 GEMM (3-stage, 1 barrier/iter) ------------
// C = A(bf16)[M,K] @ (Wh+Wl)[K,N] + bias. 128x128 tile.
// qscale: scale Q columns (col%192 < 64) by 0.125*log2(e) in bf16 epilogue.
#define AST 40
#define BST 136
#define A_EL (128*AST)
#define B_EL (32*BST)
#define GSMEM ((3*A_EL + 6*B_EL) * 2)   // 82944 bytes
__global__ void __launch_bounds__(256, 2) gemm_bf16x2(
    const __nv_bfloat16* __restrict__ A,
    const uint16_t* __restrict__ Bh, const uint16_t* __restrict__ Bl,
    const float* __restrict__ bias,
    float* __restrict__ Cf, __nv_bfloat16* __restrict__ Cb, int N, int K,
    int qscale) {
    extern __shared__ __align__(16) uint16_t sm_[];
    uint16_t* sA  = sm_;                  // 3 x A_EL
    uint16_t* sBh = sm_ + 3 * A_EL;       // 3 x B_EL
    uint16_t* sBl = sBh + 3 * B_EL;
    const int tid = threadIdx.x;
    const int lane = tid & 31, warp = tid >> 5;
    const int wr = warp >> 2, wc = warp & 3;
    const size_t aRow0 = (size_t)blockIdx.y * 128;
    const int bCol0 = blockIdx.x * 128;
    const int lrow = lane & 15, lseg = lane >> 4;

    float acc[16][4];
    #pragma unroll
    for (int i = 0; i < 16; i++)
        #pragma unroll
        for (int j = 0; j < 4; j++) acc[i][j] = 0.f;

    const int nk = K / 32;
    auto load_stage = [&](int st, int kt) {
        #pragma unroll
        for (int i = 0; i < 2; i++) {
            int c = tid * 2 + i;
            int r = c >> 2, seg = c & 3;
            CP16(s2u(&sA[st * A_EL + r * AST + seg * 8]),
                 A + (aRow0 + r) * K + kt + seg * 8);
        }
        #pragma unroll
        for (int i = 0; i < 2; i++) {
            int c = tid * 2 + i;
            int r = c >> 4, seg = c & 15;
            CP16(s2u(&sBh[st * B_EL + r * BST + seg * 8]),
                 Bh + (size_t)(kt + r) * N + bCol0 + seg * 8);
            CP16(s2u(&sBl[st * B_EL + r * BST + seg * 8]),
                 Bl + (size_t)(kt + r) * N + bCol0 + seg * 8);
        }
    };
    load_stage(0, 0); CP_COMMIT;
    load_stage(1, 32); CP_COMMIT;

    int stC = 0, stL = 2;                 // compute stage, next load stage
    for (int it = 0; it < nk; it++) {
        if (it == nk - 1) { CP_WAIT(0); } else { CP_WAIT(1); }
        __syncthreads();
        if (it + 2 < nk) { load_stage(stL, (it + 2) * 32); CP_COMMIT; }
        if (++stL == 3) stL = 0;
        #pragma unroll
        for (int k16 = 0; k16 < 32; k16 += 16) {
            uint32_t a[4][4], bh[4][2], bl[4][2];
            #pragma unroll
            for (int mi = 0; mi < 4; mi++)
                LDSM4(a[mi], s2u(&sA[stC * A_EL + (wr * 64 + mi * 16 + lrow) * AST + k16 + lseg * 8]));
            #pragma unroll
            for (int np = 0; np < 2; np++) {
                uint32_t t4[4];
                LDSM4T(t4, s2u(&sBh[stC * B_EL + (k16 + lrow) * BST + wc * 32 + np * 16 + lseg * 8]));
                bh[np*2][0] = t4[0]; bh[np*2][1] = t4[1];
                bh[np*2+1][0] = t4[2]; bh[np*2+1][1] = t4[3];
                LDSM4T(t4, s2u(&sBl[stC * B_EL + (k16 + lrow) * BST + wc * 32 + np * 16 + lseg * 8]));
                bl[np*2][0] = t4[0]; bl[np*2][1] = t4[1];
                bl[np*2+1][0] = t4[2]; bl[np*2+1][1] = t4[3];
            }
            #pragma unroll
            for (int mi = 0; mi < 4; mi++)
                #pragma unroll
                for (int ni = 0; ni < 4; ni++) {
                    MMA_BF16(acc[mi * 4 + ni], a[mi], bh[ni]);
                    MMA_BF16(acc[mi * 4 + ni], a[mi], bl[ni]);
                }
        }
        if (++stC == 3) stC = 0;
    }
    #pragma unroll
    for (int mi = 0; mi < 4; mi++) {
        size_t row = aRow0 + wr * 64 + mi * 16 + (lane >> 2);
        #pragma unroll
        for (int ni = 0; ni < 4; ni++) {
            int col = bCol0 + wc * 32 + ni * 8 + (lane & 3) * 2;
            float b0 = 0.f, b1 = 0.f;
            if (bias) { b0 = bias[col]; b1 = bias[col + 1]; }
            float* c = acc[mi * 4 + ni];
            float v00 = c[0] + b0, v01 = c[1] + b1;
            float v10 = c[2] + b0, v11 = c[3] + b1;
            if (Cf) {
                *(float2*)&Cf[row * N + col] = make_float2(v00, v01);
                *(float2*)&Cf[(row + 8) * N + col] = make_float2(v10, v11);
            }
            if (Cb) {
                // Q columns pre-scaled by 1/8 * log2(e) so flash can use ex2 directly
                float sc = (qscale && ((col % 192) < 64)) ? 0.1803368801f : 1.0f;
                *(__nv_bfloat162*)&Cb[row * N + col] =
                    __floats2bfloat162_rn(v00 * sc, v01 * sc);
                *(__nv_bfloat162*)&Cb[(row + 8) * N + col] =
                    __floats2bfloat162_rn(v10 * sc, v11 * sc);
            }
        }
    }
}

// ---------------- fused flash attention (3-stage KV, shift-free ex2) ---------
#define KST 72
#define FSMEM ((128*KST + 3*64*KST*2) * 2)   // 73728 bytes
__global__ void __launch_bounds__(256) flash_kernel(
    const __nv_bfloat16* __restrict__ qkvb, __nv_bfloat16* __restrict__ ob) {
    extern __shared__ __align__(16) __nv_bfloat16 fsm_[];
    __nv_bfloat16* sQ = fsm_;                  // 128 x KST
    __nv_bfloat16* sK = fsm_ + 128 * KST;      // 3 x 64 x KST
    __nv_bfloat16* sV = sK + 3 * 64 * KST;
    const int bh = blockIdx.y;
    const int b = bh >> 3, h = bh & 7;
    const int q0 = blockIdx.x * 128;
    const int tid = threadIdx.x, lane = tid & 31, warp = tid >> 5;
    const __nv_bfloat16* qb = qkvb + (size_t)(b * S_) * 1536 + h * 192;
    const __nv_bfloat16* kb = qb + 64;
    const __nv_bfloat16* vb = qb + 128;

    auto load_kv = [&](int buf, int t) {
        #pragma unroll
        for (int i = 0; i < 2; i++) {
            int c = tid + i * 256;
            int r = c >> 3, seg = c & 7;
            CP16(s2u(&sK[buf * 64 * KST + r * KST + seg * 8]),
                 kb + (size_t)(t * 64 + r) * 1536 + seg * 8);
            CP16(s2u(&sV[buf * 64 * KST + r * KST + seg * 8]),
                 vb + (size_t)(t * 64 + r) * 1536 + seg * 8);
        }
    };
    // group 0: Q + KV0; group 1: KV1
    #pragma unroll
    for (int i = 0; i < 4; i++) {
        int c = tid + i * 256;
        int r = c >> 3, seg = c & 7;
        CP16(s2u(&sQ[r * KST + seg * 8]), qb + (size_t)(q0 + r) * 1536 + seg * 8);
    }
    load_kv(0, 0); CP_COMMIT;
    load_kv(1, 1); CP_COMMIT;
    CP_WAIT(1);
    __syncthreads();

    uint32_t qf[4][4];
    const int qr = warp * 16;
    #pragma unroll
    for (int kk = 0; kk < 4; kk++)
        LDSM4(qf[kk], s2u(&sQ[(qr + (lane & 15)) * KST + kk * 16 + (lane >> 4) * 8]));

    float o[8][4];
    #pragma unroll
    for (int i = 0; i < 8; i++)
        #pragma unroll
        for (int j = 0; j < 4; j++) o[i][j] = 0.f;
    float l0 = 0.f, l1 = 0.f;   // exp sums (shift-free; logits bounded, log2 domain)

    const int kRow = ((lane >> 4) & 1) * 8 + (lane & 7);
    const int kCol = ((lane >> 3) & 1) * 8;
    const int vRow = ((lane >> 3) & 1) * 8 + (lane & 7);
    const int vCol = ((lane >> 4) & 1) * 8;

    int stC = 0, stL = 2;
    for (int t = 0; t < 16; t++) {
        if (t == 15) { CP_WAIT(0); } else { CP_WAIT(1); }
        __syncthreads();
        if (t + 2 < 16) { load_kv(stL, t + 2); CP_COMMIT; }
        if (++stL == 3) stL = 0;
        const int kbuf = stC * 64 * KST;
        if (++stC == 3) stC = 0;

        // S = Q K^T  (Q pre-scaled by log2e/8)
        float s[8][4];
        #pragma unroll
        for (int i = 0; i < 8; i++)
            #pragma unroll
            for (int j = 0; j < 4; j++) s[i][j] = 0.f;
        #pragma unroll
        for (int kk = 0; kk < 4; kk++) {
            uint32_t kf[8][2];
            #pragma unroll
            for (int nf2 = 0; nf2 < 4; nf2++) {
                uint32_t t4[4];
                LDSM4(t4, s2u(&sK[kbuf + (nf2 * 16 + kRow) * KST + kk * 16 + kCol]));
                kf[nf2*2][0] = t4[0]; kf[nf2*2][1] = t4[1];
                kf[nf2*2+1][0] = t4[2]; kf[nf2*2+1][1] = t4[3];
            }
            #pragma unroll
            for (int nf = 0; nf < 8; nf++)
                MMA_BF16(s[nf], qf[kk], kf[nf]);
        }

        // P = 2^S; accumulate row sums
        float rs0 = 0.f, rs1 = 0.f;
        #pragma unroll
        for (int nf = 0; nf < 8; nf++) {
            s[nf][0] = ex2f(s[nf][0]);
            s[nf][1] = ex2f(s[nf][1]);
            s[nf][2] = ex2f(s[nf][2]);
            s[nf][3] = ex2f(s[nf][3]);
            rs0 += s[nf][0] + s[nf][1];
            rs1 += s[nf][2] + s[nf][3];
        }
        rs0 += __shfl_xor_sync(0xffffffffu, rs0, 1);
        rs0 += __shfl_xor_sync(0xffffffffu, rs0, 2);
        rs1 += __shfl_xor_sync(0xffffffffu, rs1, 1);
        rs1 += __shfl_xor_sync(0xffffffffu, rs1, 2);
        l0 += rs0;
        l1 += rs1;

        // O += P V
        #pragma unroll
        for (int kk = 0; kk < 4; kk++) {
            uint32_t pa[4];
            __nv_bfloat162 p0 = __floats2bfloat162_rn(s[2*kk][0], s[2*kk][1]);
            __nv_bfloat162 p1 = __floats2bfloat162_rn(s[2*kk][2], s[2*kk][3]);
            __nv_bfloat162 p2 = __floats2bfloat162_rn(s[2*kk+1][0], s[2*kk+1][1]);
            __nv_bfloat162 p3 = __floats2bfloat162_rn(s[2*kk+1][2], s[2*kk+1][3]);
            pa[0] = *(uint32_t*)&p0; pa[1] = *(uint32_t*)&p1;
            pa[2] = *(uint32_t*)&p2; pa[3] = *(uint32_t*)&p3;
            uint32_t vf[8][2];
            #pragma unroll
            for (int nf2 = 0; nf2 < 4; nf2++) {
                uint32_t t4[4];
                LDSM4T(t4, s2u(&sV[kbuf + (kk * 16 + vRow) * KST + nf2 * 16 + vCol]));
                vf[nf2*2][0] = t4[0]; vf[nf2*2][1] = t4[1];
                vf[nf2*2+1][0] = t4[2]; vf[nf2*2+1][1] = t4[3];
            }
            #pragma unroll
            for (int nf = 0; nf < 8; nf++)
                MMA_BF16(o[nf], pa, vf[nf]);
        }
    }

    float inv0 = 1.f / l0, inv1 = 1.f / l1;
    size_t r0 = (size_t)b * S_ + q0 + qr + (lane >> 2);
    size_t r1 = r0 + 8;
    #pragma unroll
    for (int nf = 0; nf < 8; nf++) {
        int col = h * 64 + nf * 8 + (lane & 3) * 2;
        *(__nv_bfloat162*)&ob[r0 * D_ + col] =
            __floats2bfloat162_rn(o[nf][0] * inv0, o[nf][1] * inv0);
        *(__nv_bfloat162*)&ob[r1 * D_ + col] =
            __floats2bfloat162_rn(o[nf][2] * inv1, o[nf][3] * inv1);
    }
}

// ---------------- embedding + sinusoidal PE ----------------------------------
__global__ void __launch_bounds__(256) embed_kernel(const int* __restrict__ tokens,
                                                    const float* __restrict__ emb) {
    int idx = blockIdx.x * 256 + threadIdx.x;
    int d = idx & (D_ - 1);
    int bs = idx >> 9;
    int s = bs & (S_ - 1);
    int tok = tokens[bs];
    float div = expf((float)(d & ~1) * (-9.210340371976184f / (float)D_));
    float ang = (float)s * div;
    float pe = (d & 1) ? cosf(ang) : sinf(ang);
    float v = emb[(size_t)tok * D_ + d] + pe;
    g_x[idx] = v;
    g_xb[idx] = __float2bfloat16(v);
}

// ---------------- residual + bias + LayerNorm --------------------------------
__global__ void __launch_bounds__(128) ln_kernel(const float* __restrict__ bias,
                                                 const float* __restrict__ gamma,
                                                 const float* __restrict__ beta) {
    size_t r = blockIdx.x;
    int tid = threadIdx.x;
    float4 o = *(float4*)(g_p + r * D_ + tid * 4);
    float4 xr = *(float4*)(g_x + r * D_ + tid * 4);
    float4 bb = *(const float4*)(bias + tid * 4);
    float4 y;
    y.x = o.x + xr.x + bb.x; y.y = o.y + xr.y + bb.y;
    y.z = o.z + xr.z + bb.z; y.w = o.w + xr.w + bb.w;
    __shared__ float sm[4], ss[4];
    float s = y.x + y.y + y.z + y.w;
    #pragma unroll
    for (int o2 = 16; o2; o2 >>= 1) s += __shfl_xor_sync(0xffffffffu, s, o2);
    if ((tid & 31) == 0) sm[tid >> 5] = s;
    __syncthreads();
    float mean = (sm[0] + sm[1] + sm[2] + sm[3]) * (1.0f / D_);
    float dx = y.x - mean, dy = y.y - mean, dz = y.z - mean, dw = y.w - mean;
    float sq = dx*dx + dy*dy + dz*dz + dw*dw;
    #pragma unroll
    for (int o2 = 16; o2; o2 >>= 1) sq += __shfl_xor_sync(0xffffffffu, sq, o2);
    if ((tid & 31) == 0) ss[tid >> 5] = sq;
    __syncthreads();
    float var = (ss[0] + ss[1] + ss[2] + ss[3]) * (1.0f / D_);
    float inv = rsqrtf(var + 1e-5f);
    float4 g = *(const float4*)(gamma + tid * 4);
    float4 be = *(const float4*)(beta + tid * 4);
    float4 out;
    out.x = dx * inv * g.x + be.x; out.y = dy * inv * g.y + be.y;
    out.z = dz * inv * g.z + be.z; out.w = dw * inv * g.w + be.w;
    *(float4*)(g_x + r * D_ + tid * 4) = out;
    *(__nv_bfloat162*)&g_xb[r * D_ + tid * 4]     = __floats2bfloat162_rn(out.x, out.y);
    *(__nv_bfloat162*)&g_xb[r * D_ + tid * 4 + 2] = __floats2bfloat162_rn(out.z, out.w);
}

// ---------------- mean pool / MLP ---------------------------------------------
__global__ void __launch_bounds__(512) pool_kernel() {
    int b = blockIdx.x, d = threadIdx.x;
    const float* base = g_x + (size_t)b * S_ * D_ + d;
    float s = 0.f;
    for (int i = 0; i < S_; i++) s += base[(size_t)i * D_];
    g_pool[b * D_ + d] = s * (1.0f / S_);
}

__global__ void __launch_bounds__(256) mlp1_kernel(const float* __restrict__ w,
                                                   const float* __restrict__ bias) {
    int f = blockIdx.x * 256 + threadIdx.x;
    int b = blockIdx.y;
    float acc = bias[f];
    const float* pr = g_pool + b * D_;
    for (int d = 0; d < D_; d++) acc = fmaf(pr[d], w[(size_t)d * FF_ + f], acc);
    g_h1[b * FF_ + f] = fmaxf(acc, 0.f);
}

__global__ void __launch_bounds__(192) mlp2_kernel(const float* __restrict__ w,
                                                   const float* __restrict__ bias,
                                                   float* __restrict__ out) {
    int t = threadIdx.x;
    int b = t / C_, c = t % C_;
    float acc = bias[c];
    const float* hr = g_h1 + b * FF_;
    for (int f = 0; f < FF_; f++) acc = fmaf(hr[f], w[f * C_ + c], acc);
    out[b * C_ + c] = acc;
}

// ---------------- launch ------------------------------------------------------
extern "C" void kernel_launch(void* const* d_in, const int* in_sizes, int n_in,
                              void* d_out, int out_size) {
    const int*   tokens = (const int*)d_in[0];
    const float* emb    = (const float*)d_in[1];
    const float* qkv_w  = (const float*)d_in[2];
    const float* qkv_b  = (const float*)d_in[3];
    const float* fc_w   = (const float*)d_in[4];
    const float* fc_b   = (const float*)d_in[5];
    const float* gamma  = (const float*)d_in[6];
    const float* beta   = (const float*)d_in[7];
    const float* fc1_w  = (const float*)d_in[8];
    const float* fc1_b  = (const float*)d_in[9];
    const float* fc2_w  = (const float*)d_in[10];
    const float* fc2_b  = (const float*)d_in[11];
    float* out = (float*)d_out;
    (void)in_sizes; (void)n_in; (void)out_size;

    cudaFuncSetAttribute(gemm_bf16x2, cudaFuncAttributeMaxDynamicSharedMemorySize, GSMEM);
    cudaFuncSetAttribute(flash_kernel, cudaFuncAttributeMaxDynamicSharedMemorySize, FSMEM);

    __nv_bfloat16 *xb, *qkvb, *obf;
    float *p;
    uint16_t *wh, *wl;
    cudaGetSymbolAddress((void**)&xb,   g_xb);
    cudaGetSymbolAddress((void**)&qkvb, g_qkvb);
    cudaGetSymbolAddress((void**)&obf,  g_ob);
    cudaGetSymbolAddress((void**)&p,    g_p);
    cudaGetSymbolAddress((void**)&wh,   g_wh);
    cudaGetSymbolAddress((void**)&wl,   g_wl);

    embed_kernel<<<(BS_ * D_) / 256, 256>>>(tokens, emb);

    // all weight converts up-front (independent of layer compute chain)
    for (int l = 0; l < L_; l++) {
        convert_hl<<<(D_ * 3 * D_) / 1024, 256>>>(
            qkv_w + (size_t)l * D_ * 3 * D_, wh + WQKV_OFF(l), wl + WQKV_OFF(l));
        convert_hl<<<(D_ * D_) / 1024, 256>>>(
            fc_w + (size_t)l * D_ * D_, wh + WFC_OFF(l), wl + WFC_OFF(l));
    }

    for (int l = 0; l < L_; l++) {
        gemm_bf16x2<<<dim3(3 * D_ / 128, BS_ / 128), 256, GSMEM>>>(
            xb, wh + WQKV_OFF(l), wl + WQKV_OFF(l), qkv_b + (size_t)l * 3 * D_,
            (float*)nullptr, qkvb, 3 * D_, D_, 1);
        flash_kernel<<<dim3(S_ / 128, B_ * H_), 256, FSMEM>>>(qkvb, obf);
        gemm_bf16x2<<<dim3(D_ / 128, BS_ / 128), 256, GSMEM>>>(
            obf, wh + WFC_OFF(l), wl + WFC_OFF(l), (const float*)nullptr,
            p, (__nv_bfloat16*)nullptr, D_, D_, 0);
        ln_kernel<<<BS_, 128>>>(fc_b + (size_t)l * D_, gamma, beta);
    }

    pool_kernel<<<B_, 512>>>();
    mlp1_kernel<<<dim3(FF_ / 256, B_), 256>>>(fc1_w, fc1_b);
    mlp2_kernel<<<1, B_ * C_>>>(fc2_w, fc2_b, out);
}